// round 1
// baseline (speedup 1.0000x reference)
#include <cuda_runtime.h>

// NNUE HalfKP forward:
//   stm_ft  = ft_b  + sum_f v[b,f] * ft_w [stm_idx[b,f]]
//   vstm_ft = fft_b + sum_f v[b,f] * fft_w[stm_idx[b,f] % 640]
//   (same for nstm)
//   hidden = clip(concat(stm_ft+vstm_ft, nstm_ft+vnstm_ft), 0, 1)   [B, 512]
//   out    = sigmoid(hidden @ out_w.T + out_b)                      [B, 1]
//
// Mapping: one warp per batch element. Lane l owns output dims [8l, 8l+8)
// as two float4 accumulators per side. Per feature, index/value broadcast
// via shuffle; the warp's float4 gathers cover the full contiguous 1024B
// embedding row -> perfectly coalesced L2 sectors.

constexpr int FT_OUT  = 256;
constexpr int NUM_FFT = 640;
constexpr int MAXF    = 32;

__global__ __launch_bounds__(256) void nnue_halfkp_kernel(
    const float* __restrict__ values,        // [B, 32]
    const int*   __restrict__ stm_indices,   // [B, 32]
    const int*   __restrict__ nstm_indices,  // [B, 32]
    const float* __restrict__ ft_w,          // [40960, 256]
    const float* __restrict__ ft_b,          // [256]
    const float* __restrict__ fft_w,         // [640, 256]
    const float* __restrict__ fft_b,         // [256]
    const float* __restrict__ out_w,         // [1, 512]
    const float* __restrict__ out_b,         // [1]
    float*       __restrict__ out,           // [B, 1]
    int batch)
{
    const int warp_id = (blockIdx.x * blockDim.x + threadIdx.x) >> 5;
    const int lane    = threadIdx.x & 31;
    if (warp_id >= batch) return;

    // Each lane pre-loads one feature slot; broadcast later via shuffle.
    const float v_l   = values[warp_id * MAXF + lane];
    const int   is_l  = stm_indices[warp_id * MAXF + lane];
    const int   in_l  = nstm_indices[warp_id * MAXF + lane];
    const int   ism_l = is_l % NUM_FFT;
    const int   inm_l = in_l % NUM_FFT;

    const int col = lane * 8;   // this lane's 8 output dims

    float acc_s[8];
    float acc_n[8];
#pragma unroll
    for (int j = 0; j < 8; ++j) { acc_s[j] = 0.f; acc_n[j] = 0.f; }

#pragma unroll 4
    for (int f = 0; f < MAXF; ++f) {
        const float vf   = __shfl_sync(0xffffffffu, v_l,   f);
        const int   i_s  = __shfl_sync(0xffffffffu, is_l,  f);
        const int   i_n  = __shfl_sync(0xffffffffu, in_l,  f);
        const int   i_sm = __shfl_sync(0xffffffffu, ism_l, f);
        const int   i_nm = __shfl_sync(0xffffffffu, inm_l, f);

        const float4* ps  = reinterpret_cast<const float4*>(ft_w  + (size_t)i_s  * FT_OUT + col);
        const float4* psf = reinterpret_cast<const float4*>(fft_w + (size_t)i_sm * FT_OUT + col);
        const float4* pn  = reinterpret_cast<const float4*>(ft_w  + (size_t)i_n  * FT_OUT + col);
        const float4* pnf = reinterpret_cast<const float4*>(fft_w + (size_t)i_nm * FT_OUT + col);

        const float4 a0 = ps[0],  a1 = ps[1];
        const float4 b0 = psf[0], b1 = psf[1];
        const float4 c0 = pn[0],  c1 = pn[1];
        const float4 d0 = pnf[0], d1 = pnf[1];

        // acc += v * (ft_row + fft_row)
        acc_s[0] += vf * (a0.x + b0.x);
        acc_s[1] += vf * (a0.y + b0.y);
        acc_s[2] += vf * (a0.z + b0.z);
        acc_s[3] += vf * (a0.w + b0.w);
        acc_s[4] += vf * (a1.x + b1.x);
        acc_s[5] += vf * (a1.y + b1.y);
        acc_s[6] += vf * (a1.z + b1.z);
        acc_s[7] += vf * (a1.w + b1.w);

        acc_n[0] += vf * (c0.x + d0.x);
        acc_n[1] += vf * (c0.y + d0.y);
        acc_n[2] += vf * (c0.z + d0.z);
        acc_n[3] += vf * (c0.w + d0.w);
        acc_n[4] += vf * (c1.x + d1.x);
        acc_n[5] += vf * (c1.y + d1.y);
        acc_n[6] += vf * (c1.z + d1.z);
        acc_n[7] += vf * (c1.w + d1.w);
    }

    // Epilogue: bias, clip to [0,1], dot with out_w, warp-reduce, sigmoid.
    const float4 fb0  = *reinterpret_cast<const float4*>(ft_b  + col);
    const float4 fb1  = *reinterpret_cast<const float4*>(ft_b  + col + 4);
    const float4 ffb0 = *reinterpret_cast<const float4*>(fft_b + col);
    const float4 ffb1 = *reinterpret_cast<const float4*>(fft_b + col + 4);
    const float4 ws0  = *reinterpret_cast<const float4*>(out_w + col);
    const float4 ws1  = *reinterpret_cast<const float4*>(out_w + col + 4);
    const float4 wn0  = *reinterpret_cast<const float4*>(out_w + FT_OUT + col);
    const float4 wn1  = *reinterpret_cast<const float4*>(out_w + FT_OUT + col + 4);

    float bias[8] = { fb0.x + ffb0.x, fb0.y + ffb0.y, fb0.z + ffb0.z, fb0.w + ffb0.w,
                      fb1.x + ffb1.x, fb1.y + ffb1.y, fb1.z + ffb1.z, fb1.w + ffb1.w };
    float wsd[8]  = { ws0.x, ws0.y, ws0.z, ws0.w, ws1.x, ws1.y, ws1.z, ws1.w };
    float wnd[8]  = { wn0.x, wn0.y, wn0.z, wn0.w, wn1.x, wn1.y, wn1.z, wn1.w };

    float dot = 0.f;
#pragma unroll
    for (int j = 0; j < 8; ++j) {
        float hs = fminf(fmaxf(acc_s[j] + bias[j], 0.f), 1.f);
        float hn = fminf(fmaxf(acc_n[j] + bias[j], 0.f), 1.f);
        dot += hs * wsd[j] + hn * wnd[j];
    }

#pragma unroll
    for (int off = 16; off > 0; off >>= 1)
        dot += __shfl_xor_sync(0xffffffffu, dot, off);

    if (lane == 0) {
        const float x = dot + out_b[0];
        out[warp_id] = 1.0f / (1.0f + expf(-x));
    }
}

extern "C" void kernel_launch(void* const* d_in, const int* in_sizes, int n_in,
                              void* d_out, int out_size)
{
    const float* values = (const float*)d_in[0];
    const int*   stm    = (const int*)  d_in[1];
    const int*   nstm   = (const int*)  d_in[2];
    const float* ft_w   = (const float*)d_in[3];
    const float* ft_b   = (const float*)d_in[4];
    const float* fft_w  = (const float*)d_in[5];
    const float* fft_b  = (const float*)d_in[6];
    const float* out_w  = (const float*)d_in[7];
    const float* out_b  = (const float*)d_in[8];
    float* out = (float*)d_out;

    const int batch = in_sizes[0] / MAXF;          // 8192
    const int warps_per_block = 256 / 32;          // 8
    const int blocks = (batch + warps_per_block - 1) / warps_per_block;

    nnue_halfkp_kernel<<<blocks, 256>>>(values, stm, nstm, ft_w, ft_b,
                                        fft_w, fft_b, out_w, out_b, out, batch);
}

// round 2
// speedup vs baseline: 1.2907x; 1.2907x over previous
#include <cuda_runtime.h>

// NNUE HalfKP forward.
// Mapping: TWO warps per batch element (warp parity = side: 0=stm, 1=nstm).
// Lane l owns output cols {4l..4l+3} and {128+4l..128+4l+3}, so each
// warp-wide LDG.128 covers a fully contiguous 512B half-row: every 32B
// sector is requested exactly once (the previous lane*8 layout touched
// every sector twice). Sides are combined through shared memory.

constexpr int FT_OUT  = 256;
constexpr int HALF    = 128;
constexpr int NUM_FFT = 640;
constexpr int MAXF    = 32;

__global__ __launch_bounds__(256) void nnue_halfkp_kernel(
    const float* __restrict__ values,        // [B, 32]
    const int*   __restrict__ stm_indices,   // [B, 32]
    const int*   __restrict__ nstm_indices,  // [B, 32]
    const float* __restrict__ ft_w,          // [40960, 256]
    const float* __restrict__ ft_b,          // [256]
    const float* __restrict__ fft_w,         // [640, 256]
    const float* __restrict__ fft_b,         // [256]
    const float* __restrict__ out_w,         // [1, 512]
    const float* __restrict__ out_b,         // [1]
    float*       __restrict__ out,           // [B, 1]
    int batch)
{
    __shared__ float s_dot[8];               // one partial dot per warp

    const int warp = threadIdx.x >> 5;       // 0..7
    const int lane = threadIdx.x & 31;
    const int elem = blockIdx.x * 4 + (warp >> 1);
    const int side = warp & 1;                // 0 = stm, 1 = nstm
    const bool valid = elem < batch;
    const int e = valid ? elem : (batch - 1); // clamp to keep loads in-bounds

    const int* __restrict__ idx = side ? nstm_indices : stm_indices;

    // Lane pre-loads one feature slot; broadcast via shuffle inside the loop.
    const float v_l  = values[e * MAXF + lane];
    const int   i_l  = idx[e * MAXF + lane];
    const int   im_l = i_l % NUM_FFT;

    const int c0 = lane * 4;           // cols [4l, 4l+4)
    const int c1 = HALF + lane * 4;    // cols [128+4l, 128+4l+4)

    float acc[8];
#pragma unroll
    for (int j = 0; j < 8; ++j) acc[j] = 0.f;

#pragma unroll 8
    for (int f = 0; f < MAXF; ++f) {
        const float vf = __shfl_sync(0xffffffffu, v_l,  f);
        const int   i  = __shfl_sync(0xffffffffu, i_l,  f);
        const int   im = __shfl_sync(0xffffffffu, im_l, f);

        const float* pf = ft_w  + (size_t)i  * FT_OUT;
        const float* pg = fft_w + (size_t)im * FT_OUT;

        const float4 a0 = *reinterpret_cast<const float4*>(pf + c0);
        const float4 a1 = *reinterpret_cast<const float4*>(pf + c1);
        const float4 b0 = *reinterpret_cast<const float4*>(pg + c0);
        const float4 b1 = *reinterpret_cast<const float4*>(pg + c1);

        acc[0] += vf * (a0.x + b0.x);
        acc[1] += vf * (a0.y + b0.y);
        acc[2] += vf * (a0.z + b0.z);
        acc[3] += vf * (a0.w + b0.w);
        acc[4] += vf * (a1.x + b1.x);
        acc[5] += vf * (a1.y + b1.y);
        acc[6] += vf * (a1.z + b1.z);
        acc[7] += vf * (a1.w + b1.w);
    }

    // Epilogue: bias, clip [0,1], dot with this side's half of out_w.
    const float4 fb0  = *reinterpret_cast<const float4*>(ft_b  + c0);
    const float4 fb1  = *reinterpret_cast<const float4*>(ft_b  + c1);
    const float4 ffb0 = *reinterpret_cast<const float4*>(fft_b + c0);
    const float4 ffb1 = *reinterpret_cast<const float4*>(fft_b + c1);
    const float* w    = out_w + side * FT_OUT;
    const float4 w0   = *reinterpret_cast<const float4*>(w + c0);
    const float4 w1   = *reinterpret_cast<const float4*>(w + c1);

    const float bias[8] = { fb0.x + ffb0.x, fb0.y + ffb0.y, fb0.z + ffb0.z, fb0.w + ffb0.w,
                            fb1.x + ffb1.x, fb1.y + ffb1.y, fb1.z + ffb1.z, fb1.w + ffb1.w };
    const float wd[8]   = { w0.x, w0.y, w0.z, w0.w, w1.x, w1.y, w1.z, w1.w };

    float dot = 0.f;
#pragma unroll
    for (int j = 0; j < 8; ++j) {
        const float h = fminf(fmaxf(acc[j] + bias[j], 0.f), 1.f);
        dot += h * wd[j];
    }

#pragma unroll
    for (int off = 16; off > 0; off >>= 1)
        dot += __shfl_xor_sync(0xffffffffu, dot, off);

    if (lane == 0) s_dot[warp] = dot;
    __syncthreads();

    if (threadIdx.x < 4) {
        const int eo = blockIdx.x * 4 + threadIdx.x;
        if (eo < batch) {
            const float x = s_dot[2 * threadIdx.x] + s_dot[2 * threadIdx.x + 1] + out_b[0];
            out[eo] = 1.0f / (1.0f + expf(-x));
        }
    }
}

extern "C" void kernel_launch(void* const* d_in, const int* in_sizes, int n_in,
                              void* d_out, int out_size)
{
    const float* values = (const float*)d_in[0];
    const int*   stm    = (const int*)  d_in[1];
    const int*   nstm   = (const int*)  d_in[2];
    const float* ft_w   = (const float*)d_in[3];
    const float* ft_b   = (const float*)d_in[4];
    const float* fft_w  = (const float*)d_in[5];
    const float* fft_b  = (const float*)d_in[6];
    const float* out_w  = (const float*)d_in[7];
    const float* out_b  = (const float*)d_in[8];
    float* out = (float*)d_out;

    const int batch  = in_sizes[0] / MAXF;   // 8192
    const int blocks = (batch + 3) / 4;      // 4 elements per 256-thread block

    nnue_halfkp_kernel<<<blocks, 256>>>(values, stm, nstm, ft_w, ft_b,
                                        fft_w, fft_b, out_w, out_b, out, batch);
}

// round 4
// speedup vs baseline: 1.9530x; 1.5132x over previous
#include <cuda_runtime.h>
#include <cuda_fp16.h>

// NNUE HalfKP forward, fp16-table edition.
// Stage 1 (per launch, graph-captured): convert ft_w / fft_w fp32 -> fp16
//   into __device__ scratch (no allocations). ~63MB of traffic, ~7us.
// Stage 2: gather kernel. Two warps per batch element (warp parity = side).
//   Lane l owns output cols [8l, 8l+8) = 8 halves = 16B, so each table row
//   is fetched by ONE warp-wide LDG.128 covering the full contiguous 512B
//   row -- every 32B sector touched exactly once. Accumulation in fp32.

constexpr int FT_OUT  = 256;
constexpr int NUM_FT  = 40960;
constexpr int NUM_FFT = 640;
constexpr int MAXF    = 32;

__device__ __half g_ft_h [(size_t)NUM_FT  * FT_OUT];   // 20 MB
__device__ __half g_fft_h[(size_t)NUM_FFT * FT_OUT];   // 320 KB

__global__ __launch_bounds__(256) void convert_kernel(
    const float* __restrict__ src, __half* __restrict__ dst, int n8)
{
    const int i = blockIdx.x * blockDim.x + threadIdx.x;
    if (i >= n8) return;
    const float4* s = reinterpret_cast<const float4*>(src) + 2 * (size_t)i;
    const float4 a = s[0];
    const float4 b = s[1];
    __half2 h0 = __floats2half2_rn(a.x, a.y);
    __half2 h1 = __floats2half2_rn(a.z, a.w);
    __half2 h2 = __floats2half2_rn(b.x, b.y);
    __half2 h3 = __floats2half2_rn(b.z, b.w);
    uint4 packed;
    packed.x = *reinterpret_cast<unsigned int*>(&h0);
    packed.y = *reinterpret_cast<unsigned int*>(&h1);
    packed.z = *reinterpret_cast<unsigned int*>(&h2);
    packed.w = *reinterpret_cast<unsigned int*>(&h3);
    reinterpret_cast<uint4*>(dst)[i] = packed;
}

__global__ __launch_bounds__(256) void nnue_halfkp_kernel(
    const float* __restrict__ values,        // [B, 32]
    const int*   __restrict__ stm_indices,   // [B, 32]
    const int*   __restrict__ nstm_indices,  // [B, 32]
    const float* __restrict__ ft_b,          // [256]
    const float* __restrict__ fft_b,         // [256]
    const float* __restrict__ out_w,         // [1, 512]
    const float* __restrict__ out_b,         // [1]
    float*       __restrict__ out,           // [B, 1]
    int batch)
{
    __shared__ float s_dot[8];

    const int warp = threadIdx.x >> 5;        // 0..7
    const int lane = threadIdx.x & 31;
    const int elem = blockIdx.x * 4 + (warp >> 1);
    const int side = warp & 1;                 // 0 = stm, 1 = nstm
    const int e    = (elem < batch) ? elem : (batch - 1);

    const int* __restrict__ idx = side ? nstm_indices : stm_indices;

    const float v_l  = values[e * MAXF + lane];
    const int   i_l  = idx[e * MAXF + lane];
    const int   im_l = i_l % NUM_FFT;

    const int col = lane * 8;   // this lane's 8 output dims

    float acc[8];
#pragma unroll
    for (int j = 0; j < 8; ++j) acc[j] = 0.f;

#pragma unroll 8
    for (int f = 0; f < MAXF; ++f) {
        const float vf = __shfl_sync(0xffffffffu, v_l,  f);
        const int   i  = __shfl_sync(0xffffffffu, i_l,  f);
        const int   im = __shfl_sync(0xffffffffu, im_l, f);

        const uint4 pa = *reinterpret_cast<const uint4*>(g_ft_h  + (size_t)i  * FT_OUT + col);
        const uint4 pb = *reinterpret_cast<const uint4*>(g_fft_h + (size_t)im * FT_OUT + col);

        const __half2 a0 = *reinterpret_cast<const __half2*>(&pa.x);
        const __half2 a1 = *reinterpret_cast<const __half2*>(&pa.y);
        const __half2 a2 = *reinterpret_cast<const __half2*>(&pa.z);
        const __half2 a3 = *reinterpret_cast<const __half2*>(&pa.w);
        const __half2 b0 = *reinterpret_cast<const __half2*>(&pb.x);
        const __half2 b1 = *reinterpret_cast<const __half2*>(&pb.y);
        const __half2 b2 = *reinterpret_cast<const __half2*>(&pb.z);
        const __half2 b3 = *reinterpret_cast<const __half2*>(&pb.w);

        const float2 f0 = __half22float2(__hadd2(a0, b0));
        const float2 f1 = __half22float2(__hadd2(a1, b1));
        const float2 f2 = __half22float2(__hadd2(a2, b2));
        const float2 f3 = __half22float2(__hadd2(a3, b3));

        acc[0] += vf * f0.x;
        acc[1] += vf * f0.y;
        acc[2] += vf * f1.x;
        acc[3] += vf * f1.y;
        acc[4] += vf * f2.x;
        acc[5] += vf * f2.y;
        acc[6] += vf * f3.x;
        acc[7] += vf * f3.y;
    }

    // Epilogue: bias (fp32 originals), clip [0,1], dot with this side's out_w.
    const float4 fb0  = *reinterpret_cast<const float4*>(ft_b  + col);
    const float4 fb1  = *reinterpret_cast<const float4*>(ft_b  + col + 4);
    const float4 ffb0 = *reinterpret_cast<const float4*>(fft_b + col);
    const float4 ffb1 = *reinterpret_cast<const float4*>(fft_b + col + 4);
    const float* w    = out_w + side * FT_OUT;
    const float4 w0   = *reinterpret_cast<const float4*>(w + col);
    const float4 w1   = *reinterpret_cast<const float4*>(w + col + 4);

    const float bias[8] = { fb0.x + ffb0.x, fb0.y + ffb0.y, fb0.z + ffb0.z, fb0.w + ffb0.w,
                            fb1.x + ffb1.x, fb1.y + ffb1.y, fb1.z + ffb1.z, fb1.w + ffb1.w };
    const float wd[8]   = { w0.x, w0.y, w0.z, w0.w, w1.x, w1.y, w1.z, w1.w };

    float dot = 0.f;
#pragma unroll
    for (int j = 0; j < 8; ++j) {
        const float h = fminf(fmaxf(acc[j] + bias[j], 0.f), 1.f);
        dot += h * wd[j];
    }

#pragma unroll
    for (int off = 16; off > 0; off >>= 1)
        dot += __shfl_xor_sync(0xffffffffu, dot, off);

    if (lane == 0) s_dot[warp] = dot;
    __syncthreads();

    if (threadIdx.x < 4) {
        const int eo = blockIdx.x * 4 + threadIdx.x;
        if (eo < batch) {
            const float x = s_dot[2 * threadIdx.x] + s_dot[2 * threadIdx.x + 1] + out_b[0];
            out[eo] = 1.0f / (1.0f + expf(-x));
        }
    }
}

extern "C" void kernel_launch(void* const* d_in, const int* in_sizes, int n_in,
                              void* d_out, int out_size)
{
    const float* values = (const float*)d_in[0];
    const int*   stm    = (const int*)  d_in[1];
    const int*   nstm   = (const int*)  d_in[2];
    const float* ft_w   = (const float*)d_in[3];
    const float* ft_b   = (const float*)d_in[4];
    const float* fft_w  = (const float*)d_in[5];
    const float* fft_b  = (const float*)d_in[6];
    const float* out_w  = (const float*)d_in[7];
    const float* out_b  = (const float*)d_in[8];
    float* out = (float*)d_out;

    __half* ft_h_ptr  = nullptr;
    __half* fft_h_ptr = nullptr;
    cudaGetSymbolAddress((void**)&ft_h_ptr,  g_ft_h);
    cudaGetSymbolAddress((void**)&fft_h_ptr, g_fft_h);

    // Stage 1: fp32 -> fp16 table conversion (8 floats per thread).
    const int n8_ft  = (NUM_FT  * FT_OUT) / 8;   // 1,310,720
    const int n8_fft = (NUM_FFT * FT_OUT) / 8;   // 20,480
    convert_kernel<<<(n8_ft  + 255) / 256, 256>>>(ft_w,  ft_h_ptr,  n8_ft);
    convert_kernel<<<(n8_fft + 255) / 256, 256>>>(fft_w, fft_h_ptr, n8_fft);

    // Stage 2: gather + MLP.
    const int batch  = in_sizes[0] / MAXF;   // 8192
    const int blocks = (batch + 3) / 4;
    nnue_halfkp_kernel<<<blocks, 256>>>(values, stm, nstm, ft_b,
                                        fft_b, out_w, out_b, out, batch);
}

// round 5
// speedup vs baseline: 2.5998x; 1.3311x over previous
#include <cuda_runtime.h>
#include <cuda_fp16.h>

// NNUE HalfKP forward, int8 combined-table edition.
//
// Stage 1 (graph-captured, per launch): build comb[i][d] = ft_w[i][d] +
//   fft_w[i%640][d], quantize per-row to int8 (bias +128), store scale.
//   One warp per row. ~50MB traffic, L2-resident on replays.
// Stage 2: gather. Two warps per batch element (warp parity = side).
//   Lane l owns dims [8l, 8l+8) = 8 bytes -> one LDG.64 per feature; the
//   warp covers the contiguous 256B row, every sector touched once.
//   Unpack via __byte_perm + fp16 magic (0x66xx = 1536+byte), HSUB2(1664)
//   -> signed q, HFMA2 accumulate in fp16. Epilogue in fp32 with exact
//   fp32 biases.

constexpr int FT_OUT  = 256;
constexpr int NUM_FT  = 40960;
constexpr int NUM_FFT = 640;
constexpr int MAXF    = 32;

__device__ uint2 g_comb [(size_t)NUM_FT * 32];   // 10 MB int8, 8B per lane-chunk
__device__ float g_scale[NUM_FT];                // per-row dequant scale

__global__ __launch_bounds__(256) void build_table_kernel(
    const float* __restrict__ ft_w,   // [40960, 256]
    const float* __restrict__ fft_w)  // [640, 256]
{
    const int warp = threadIdx.x >> 5;
    const int lane = threadIdx.x & 31;
    const int row  = blockIdx.x * 8 + warp;
    if (row >= NUM_FT) return;

    const float* pf = ft_w  + (size_t)row * FT_OUT + lane * 8;
    const float* pg = fft_w + (size_t)(row % NUM_FFT) * FT_OUT + lane * 8;

    const float4 a0 = *reinterpret_cast<const float4*>(pf);
    const float4 a1 = *reinterpret_cast<const float4*>(pf + 4);
    const float4 b0 = *reinterpret_cast<const float4*>(pg);
    const float4 b1 = *reinterpret_cast<const float4*>(pg + 4);

    float s[8] = { a0.x + b0.x, a0.y + b0.y, a0.z + b0.z, a0.w + b0.w,
                   a1.x + b1.x, a1.y + b1.y, a1.z + b1.z, a1.w + b1.w };

    float m = 0.f;
#pragma unroll
    for (int j = 0; j < 8; ++j) m = fmaxf(m, fabsf(s[j]));
#pragma unroll
    for (int off = 16; off > 0; off >>= 1)
        m = fmaxf(m, __shfl_xor_sync(0xffffffffu, m, off));

    m = fmaxf(m, 1e-20f);
    const float inv = 127.0f / m;

    unsigned int b[8];
#pragma unroll
    for (int j = 0; j < 8; ++j) {
        int q = __float2int_rn(s[j] * inv);      // in [-127, 127]
        b[j] = (unsigned int)(q + 128) & 0xffu;  // biased byte
    }
    uint2 packed;
    packed.x = b[0] | (b[1] << 8) | (b[2] << 16) | (b[3] << 24);
    packed.y = b[4] | (b[5] << 8) | (b[6] << 16) | (b[7] << 24);

    g_comb[(size_t)row * 32 + lane] = packed;
    if (lane == 0) g_scale[row] = m * (1.0f / 127.0f);
}

__global__ __launch_bounds__(256) void nnue_halfkp_kernel(
    const float* __restrict__ values,        // [B, 32]
    const int*   __restrict__ stm_indices,   // [B, 32]
    const int*   __restrict__ nstm_indices,  // [B, 32]
    const float* __restrict__ ft_b,          // [256]
    const float* __restrict__ fft_b,         // [256]
    const float* __restrict__ out_w,         // [1, 512]
    const float* __restrict__ out_b,         // [1]
    float*       __restrict__ out,           // [B, 1]
    int batch)
{
    __shared__ float s_dot[8];

    const int warp = threadIdx.x >> 5;        // 0..7
    const int lane = threadIdx.x & 31;
    const int elem = blockIdx.x * 4 + (warp >> 1);
    const int side = warp & 1;                 // 0 = stm, 1 = nstm
    const int e    = (elem < batch) ? elem : (batch - 1);

    const int* __restrict__ idx = side ? nstm_indices : stm_indices;

    // Lane pre-loads one feature slot: index + value*scale[index].
    const float v_l  = values[e * MAXF + lane];
    const int   i_l  = idx[e * MAXF + lane];
    const float vs_l = v_l * g_scale[i_l];

    const __half2 magic_off = __float2half2_rn(1664.0f);   // 1536 + 128 bias

    __half2 acc[4];
#pragma unroll
    for (int k = 0; k < 4; ++k) acc[k] = __float2half2_rn(0.f);

#pragma unroll 8
    for (int f = 0; f < MAXF; ++f) {
        const float vs = __shfl_sync(0xffffffffu, vs_l, f);
        const int   i  = __shfl_sync(0xffffffffu, i_l,  f);

        const uint2 p = g_comb[(size_t)i * 32 + lane];
        const __half2 vsh = __float2half2_rn(vs);

        // bytes -> fp16 via magic: 0x66b.. == 1536 + byte (exact for 0..255)
        unsigned int u01 = __byte_perm(p.x, 0x66666666u, 0x4140u); // dims 0,1
        unsigned int u23 = __byte_perm(p.x, 0x66666666u, 0x4342u); // dims 2,3
        unsigned int u45 = __byte_perm(p.y, 0x66666666u, 0x4140u); // dims 4,5
        unsigned int u67 = __byte_perm(p.y, 0x66666666u, 0x4342u); // dims 6,7

        const __half2 q0 = __hsub2(*reinterpret_cast<__half2*>(&u01), magic_off);
        const __half2 q1 = __hsub2(*reinterpret_cast<__half2*>(&u23), magic_off);
        const __half2 q2 = __hsub2(*reinterpret_cast<__half2*>(&u45), magic_off);
        const __half2 q3 = __hsub2(*reinterpret_cast<__half2*>(&u67), magic_off);

        acc[0] = __hfma2(q0, vsh, acc[0]);
        acc[1] = __hfma2(q1, vsh, acc[1]);
        acc[2] = __hfma2(q2, vsh, acc[2]);
        acc[3] = __hfma2(q3, vsh, acc[3]);
    }

    const int col = lane * 8;

    const float2 f0 = __half22float2(acc[0]);
    const float2 f1 = __half22float2(acc[1]);
    const float2 f2 = __half22float2(acc[2]);
    const float2 f3 = __half22float2(acc[3]);
    const float av[8] = { f0.x, f0.y, f1.x, f1.y, f2.x, f2.y, f3.x, f3.y };

    // Epilogue: exact fp32 biases, clip [0,1], dot with this side's out_w.
    const float4 fb0  = *reinterpret_cast<const float4*>(ft_b  + col);
    const float4 fb1  = *reinterpret_cast<const float4*>(ft_b  + col + 4);
    const float4 ffb0 = *reinterpret_cast<const float4*>(fft_b + col);
    const float4 ffb1 = *reinterpret_cast<const float4*>(fft_b + col + 4);
    const float* w    = out_w + side * FT_OUT;
    const float4 w0   = *reinterpret_cast<const float4*>(w + col);
    const float4 w1   = *reinterpret_cast<const float4*>(w + col + 4);

    const float bias[8] = { fb0.x + ffb0.x, fb0.y + ffb0.y, fb0.z + ffb0.z, fb0.w + ffb0.w,
                            fb1.x + ffb1.x, fb1.y + ffb1.y, fb1.z + ffb1.z, fb1.w + ffb1.w };
    const float wd[8]   = { w0.x, w0.y, w0.z, w0.w, w1.x, w1.y, w1.z, w1.w };

    float dot = 0.f;
#pragma unroll
    for (int j = 0; j < 8; ++j) {
        const float h = fminf(fmaxf(av[j] + bias[j], 0.f), 1.f);
        dot += h * wd[j];
    }

#pragma unroll
    for (int off = 16; off > 0; off >>= 1)
        dot += __shfl_xor_sync(0xffffffffu, dot, off);

    if (lane == 0) s_dot[warp] = dot;
    __syncthreads();

    if (threadIdx.x < 4) {
        const int eo = blockIdx.x * 4 + threadIdx.x;
        if (eo < batch) {
            const float x = s_dot[2 * threadIdx.x] + s_dot[2 * threadIdx.x + 1] + out_b[0];
            out[eo] = 1.0f / (1.0f + expf(-x));
        }
    }
}

extern "C" void kernel_launch(void* const* d_in, const int* in_sizes, int n_in,
                              void* d_out, int out_size)
{
    const float* values = (const float*)d_in[0];
    const int*   stm    = (const int*)  d_in[1];
    const int*   nstm   = (const int*)  d_in[2];
    const float* ft_w   = (const float*)d_in[3];
    const float* ft_b   = (const float*)d_in[4];
    const float* fft_w  = (const float*)d_in[5];
    const float* fft_b  = (const float*)d_in[6];
    const float* out_w  = (const float*)d_in[7];
    const float* out_b  = (const float*)d_in[8];
    float* out = (float*)d_out;

    // Stage 1: combined int8 table (one warp per row, 8 rows per block).
    build_table_kernel<<<NUM_FT / 8, 256>>>(ft_w, fft_w);

    // Stage 2: gather + MLP.
    const int batch  = in_sizes[0] / MAXF;   // 8192
    const int blocks = (batch + 3) / 4;
    nnue_halfkp_kernel<<<blocks, 256>>>(values, stm, nstm, ft_b,
                                        fft_b, out_w, out_b, out, batch);
}

// round 9
// speedup vs baseline: 2.7894x; 1.0729x over previous
#include <cuda_runtime.h>
#include <cuda_fp16.h>

// NNUE HalfKP forward, int8 combined-table edition.
//
// Stage 1 (graph-captured, per launch): comb[i][d] = ft_w[i][d] +
//   fft_w[i%640][d]; per-row absmax scale; int8 with +128 bias. 10MB table.
// Stage 2: gather. Two warps per batch element (warp parity = side).
//   Per-feature {row index, value*scale as half2} precomputed into one smem
//   uint2 slot (LDS.64 broadcast). Per-lane gather address rebuilt in-loop
//   as lane_base + i*32 (one IMAD.WIDE) -- NOT stored, since the stored
//   address would be lane f's chunk, not this lane's (the R7/R8 bug).
//   Unpack: 4 PRMT (byte -> 0x66xx fp16 magic) + 4 HSUB2(1664) + 4 HFMA2.
//   fp16 accumulate, fp32 epilogue with exact fp32 biases.

constexpr int FT_OUT  = 256;
constexpr int NUM_FT  = 40960;
constexpr int NUM_FFT = 640;
constexpr int MAXF    = 32;

__device__ uint2 g_comb [(size_t)NUM_FT * 32];   // 10 MB int8, 8B per lane-chunk
__device__ float g_scale[NUM_FT];                // per-row dequant scale

__global__ __launch_bounds__(256) void build_table_kernel(
    const float* __restrict__ ft_w,   // [40960, 256]
    const float* __restrict__ fft_w)  // [640, 256]
{
    const int warp = threadIdx.x >> 5;
    const int lane = threadIdx.x & 31;
    const int row  = blockIdx.x * 8 + warp;
    if (row >= NUM_FT) return;

    const float* pf = ft_w  + (size_t)row * FT_OUT + lane * 8;
    const float* pg = fft_w + (size_t)(row % NUM_FFT) * FT_OUT + lane * 8;

    const float4 a0 = *reinterpret_cast<const float4*>(pf);
    const float4 a1 = *reinterpret_cast<const float4*>(pf + 4);
    const float4 b0 = *reinterpret_cast<const float4*>(pg);
    const float4 b1 = *reinterpret_cast<const float4*>(pg + 4);

    float s[8] = { a0.x + b0.x, a0.y + b0.y, a0.z + b0.z, a0.w + b0.w,
                   a1.x + b1.x, a1.y + b1.y, a1.z + b1.z, a1.w + b1.w };

    float m = 0.f;
#pragma unroll
    for (int j = 0; j < 8; ++j) m = fmaxf(m, fabsf(s[j]));
#pragma unroll
    for (int off = 16; off > 0; off >>= 1)
        m = fmaxf(m, __shfl_xor_sync(0xffffffffu, m, off));

    m = fmaxf(m, 1e-20f);
    const float inv = 127.0f / m;

    unsigned int b[8];
#pragma unroll
    for (int j = 0; j < 8; ++j) {
        int q = __float2int_rn(s[j] * inv);      // in [-127, 127]
        b[j] = (unsigned int)(q + 128) & 0xffu;  // biased byte
    }
    uint2 packed;
    packed.x = b[0] | (b[1] << 8) | (b[2] << 16) | (b[3] << 24);
    packed.y = b[4] | (b[5] << 8) | (b[6] << 16) | (b[7] << 24);

    g_comb[(size_t)row * 32 + lane] = packed;
    if (lane == 0) g_scale[row] = m * (1.0f / 127.0f);
}

__global__ __launch_bounds__(256) void nnue_halfkp_kernel(
    const float* __restrict__ values,        // [B, 32]
    const int*   __restrict__ stm_indices,   // [B, 32]
    const int*   __restrict__ nstm_indices,  // [B, 32]
    const float* __restrict__ ft_b,          // [256]
    const float* __restrict__ fft_b,         // [256]
    const float* __restrict__ out_w,         // [1, 512]
    const float* __restrict__ out_b,         // [1]
    float*       __restrict__ out,           // [B, 1]
    int batch)
{
    __shared__ float s_dot[8];
    __shared__ uint2 s_pre[8][32];            // per-warp: {row index, vsh bits}

    const int warp = threadIdx.x >> 5;        // 0..7
    const int lane = threadIdx.x & 31;
    const int elem = blockIdx.x * 4 + (warp >> 1);
    const int side = warp & 1;                 // 0 = stm, 1 = nstm
    const int e    = (elem < batch) ? elem : (batch - 1);

    const int* __restrict__ idx = side ? nstm_indices : stm_indices;

    // Preload: lane l prepares feature l -> {row index, value*scale fp16x2}.
    {
        const float v = values[e * MAXF + lane];
        const int   i = idx[e * MAXF + lane];
        const float vs = v * g_scale[i];
        const __half2 vsh = __float2half2_rn(vs);
        uint2 t;
        t.x = (unsigned)i;
        t.y = *reinterpret_cast<const unsigned*>(&vsh);
        s_pre[warp][lane] = t;
    }
    __syncwarp();

    // This lane's chunk base: g_comb + lane. In-loop address = lane_base + i*32.
    const uint2* __restrict__ lane_base = g_comb + lane;

    const __half2 magic_off = __float2half2_rn(1664.0f);   // 1536 + 128 bias

    __half2 acc0 = __float2half2_rn(0.f);
    __half2 acc1 = __float2half2_rn(0.f);
    __half2 acc2 = __float2half2_rn(0.f);
    __half2 acc3 = __float2half2_rn(0.f);

#pragma unroll 8
    for (int f = 0; f < MAXF; ++f) {
        const uint2 t = s_pre[warp][f];                       // LDS.64 broadcast
        const uint2 p = lane_base[(size_t)t.x * 32];          // IMAD.WIDE + LDG.64
        const __half2 vsh = *reinterpret_cast<const __half2*>(&t.y);

        // bytes -> fp16 via magic: 0x66b. == 1536 + byte (exact for 0..255)
        unsigned int u01 = __byte_perm(p.x, 0x66666666u, 0x4140u); // dims 0,1
        unsigned int u23 = __byte_perm(p.x, 0x66666666u, 0x4342u); // dims 2,3
        unsigned int u45 = __byte_perm(p.y, 0x66666666u, 0x4140u); // dims 4,5
        unsigned int u67 = __byte_perm(p.y, 0x66666666u, 0x4342u); // dims 6,7

        const __half2 q0 = __hsub2(*reinterpret_cast<__half2*>(&u01), magic_off);
        const __half2 q1 = __hsub2(*reinterpret_cast<__half2*>(&u23), magic_off);
        const __half2 q2 = __hsub2(*reinterpret_cast<__half2*>(&u45), magic_off);
        const __half2 q3 = __hsub2(*reinterpret_cast<__half2*>(&u67), magic_off);

        acc0 = __hfma2(q0, vsh, acc0);
        acc1 = __hfma2(q1, vsh, acc1);
        acc2 = __hfma2(q2, vsh, acc2);
        acc3 = __hfma2(q3, vsh, acc3);
    }

    const int col = lane * 8;

    const float2 f0 = __half22float2(acc0);
    const float2 f1 = __half22float2(acc1);
    const float2 f2 = __half22float2(acc2);
    const float2 f3 = __half22float2(acc3);
    const float av[8] = { f0.x, f0.y, f1.x, f1.y, f2.x, f2.y, f3.x, f3.y };

    // Epilogue: exact fp32 biases, clip [0,1], dot with this side's out_w.
    const float4 fb0  = *reinterpret_cast<const float4*>(ft_b  + col);
    const float4 fb1  = *reinterpret_cast<const float4*>(ft_b  + col + 4);
    const float4 ffb0 = *reinterpret_cast<const float4*>(fft_b + col);
    const float4 ffb1 = *reinterpret_cast<const float4*>(fft_b + col + 4);
    const float* w    = out_w + side * FT_OUT;
    const float4 w0   = *reinterpret_cast<const float4*>(w + col);
    const float4 w1   = *reinterpret_cast<const float4*>(w + col + 4);

    const float bias[8] = { fb0.x + ffb0.x, fb0.y + ffb0.y, fb0.z + ffb0.z, fb0.w + ffb0.w,
                            fb1.x + ffb1.x, fb1.y + ffb1.y, fb1.z + ffb1.z, fb1.w + ffb1.w };
    const float wd[8]   = { w0.x, w0.y, w0.z, w0.w, w1.x, w1.y, w1.z, w1.w };

    float dot = 0.f;
#pragma unroll
    for (int j = 0; j < 8; ++j) {
        const float h = fminf(fmaxf(av[j] + bias[j], 0.f), 1.f);
        dot += h * wd[j];
    }

#pragma unroll
    for (int off = 16; off > 0; off >>= 1)
        dot += __shfl_xor_sync(0xffffffffu, dot, off);

    if (lane == 0) s_dot[warp] = dot;
    __syncthreads();

    if (threadIdx.x < 4) {
        const int eo = blockIdx.x * 4 + threadIdx.x;
        if (eo < batch) {
            const float x = s_dot[2 * threadIdx.x] + s_dot[2 * threadIdx.x + 1] + out_b[0];
            out[eo] = 1.0f / (1.0f + expf(-x));
        }
    }
}

extern "C" void kernel_launch(void* const* d_in, const int* in_sizes, int n_in,
                              void* d_out, int out_size)
{
    const float* values = (const float*)d_in[0];
    const int*   stm    = (const int*)  d_in[1];
    const int*   nstm   = (const int*)  d_in[2];
    const float* ft_w   = (const float*)d_in[3];
    const float* ft_b   = (const float*)d_in[4];
    const float* fft_w  = (const float*)d_in[5];
    const float* fft_b  = (const float*)d_in[6];
    const float* out_w  = (const float*)d_in[7];
    const float* out_b  = (const float*)d_in[8];
    float* out = (float*)d_out;

    // Stage 1: combined int8 table (one warp per row, 8 rows per block).
    build_table_kernel<<<NUM_FT / 8, 256>>>(ft_w, fft_w);

    // Stage 2: gather + MLP.
    const int batch  = in_sizes[0] / MAXF;   // 8192
    const int blocks = (batch + 3) / 4;
    nnue_halfkp_kernel<<<blocks, 256>>>(values, stm, nstm, ft_b,
                                        fft_b, out_w, out_b, out, batch);
}

// round 10
// speedup vs baseline: 2.9937x; 1.0732x over previous
#include <cuda_runtime.h>
#include <cuda_fp16.h>
#include <cuda_fp8.h>

// NNUE HalfKP forward, e4m3 combined-table edition (addressing FIXED).
//
// Stage 1: comb[i][d] = ft_w[i][d] + fft_w[i%640][d]; per-row absmax ->
//   scale (rowmax maps to 448); e4m3 encode. 10MB table.
// Stage 2: gather. Two warps per batch element (warp parity = side).
//   Per-feature {row index, value*scale fp16x2} in smem (LDS.64 broadcast);
//   per-lane address rebuilt in-loop as lane_base + i*32 (the R7/R8 bug was
//   storing lane f's address). Decode: 4x cvt.rn.f16x2.e4m3x2 + 4 HFMA2.
//   fp16 accumulate, fp32 epilogue with exact fp32 biases.

constexpr int FT_OUT  = 256;
constexpr int NUM_FT  = 40960;
constexpr int NUM_FFT = 640;
constexpr int MAXF    = 32;

__device__ uint2 g_comb [(size_t)NUM_FT * 32];   // 10 MB e4m3, 8B per lane-chunk
__device__ float g_scale[NUM_FT];                // per-row dequant scale (m/448)

__device__ __forceinline__ __half2 dec_e4m3x2(unsigned int s) {
    __half2_raw r = __nv_cvt_fp8x2_to_halfraw2((__nv_fp8x2_storage_t)(unsigned short)s, __NV_E4M3);
    return __half2(r);
}

__global__ __launch_bounds__(256) void build_table_kernel(
    const float* __restrict__ ft_w,   // [40960, 256]
    const float* __restrict__ fft_w)  // [640, 256]
{
    const int warp = threadIdx.x >> 5;
    const int lane = threadIdx.x & 31;
    const int row  = blockIdx.x * 8 + warp;
    if (row >= NUM_FT) return;

    const float* pf = ft_w  + (size_t)row * FT_OUT + lane * 8;
    const float* pg = fft_w + (size_t)(row % NUM_FFT) * FT_OUT + lane * 8;

    const float4 a0 = *reinterpret_cast<const float4*>(pf);
    const float4 a1 = *reinterpret_cast<const float4*>(pf + 4);
    const float4 b0 = *reinterpret_cast<const float4*>(pg);
    const float4 b1 = *reinterpret_cast<const float4*>(pg + 4);

    float s[8] = { a0.x + b0.x, a0.y + b0.y, a0.z + b0.z, a0.w + b0.w,
                   a1.x + b1.x, a1.y + b1.y, a1.z + b1.z, a1.w + b1.w };

    float m = 0.f;
#pragma unroll
    for (int j = 0; j < 8; ++j) m = fmaxf(m, fabsf(s[j]));
#pragma unroll
    for (int off = 16; off > 0; off >>= 1)
        m = fmaxf(m, __shfl_xor_sync(0xffffffffu, m, off));

    m = fmaxf(m, 1e-20f);
    const float inv = 448.0f / m;

    unsigned short e[4];
#pragma unroll
    for (int j = 0; j < 4; ++j) {
        float2 pr = make_float2(s[2 * j] * inv, s[2 * j + 1] * inv);
        e[j] = (unsigned short)__nv_cvt_float2_to_fp8x2(pr, __NV_SATFINITE, __NV_E4M3);
    }
    uint2 packed;
    packed.x = (unsigned)e[0] | ((unsigned)e[1] << 16);
    packed.y = (unsigned)e[2] | ((unsigned)e[3] << 16);

    g_comb[(size_t)row * 32 + lane] = packed;
    if (lane == 0) g_scale[row] = m * (1.0f / 448.0f);
}

__global__ __launch_bounds__(256) void nnue_halfkp_kernel(
    const float* __restrict__ values,        // [B, 32]
    const int*   __restrict__ stm_indices,   // [B, 32]
    const int*   __restrict__ nstm_indices,  // [B, 32]
    const float* __restrict__ ft_b,          // [256]
    const float* __restrict__ fft_b,         // [256]
    const float* __restrict__ out_w,         // [1, 512]
    const float* __restrict__ out_b,         // [1]
    float*       __restrict__ out,           // [B, 1]
    int batch)
{
    __shared__ float s_dot[8];
    __shared__ uint2 s_pre[8][32];            // per-warp: {row index, vsh bits}

    const int warp = threadIdx.x >> 5;        // 0..7
    const int lane = threadIdx.x & 31;
    const int elem = blockIdx.x * 4 + (warp >> 1);
    const int side = warp & 1;                 // 0 = stm, 1 = nstm
    const int e    = (elem < batch) ? elem : (batch - 1);

    const int* __restrict__ idx = side ? nstm_indices : stm_indices;

    // Preload: lane l prepares feature l -> {row index, value*scale fp16x2}.
    {
        const float v = values[e * MAXF + lane];
        const int   i = idx[e * MAXF + lane];
        const float vs = v * g_scale[i];
        const __half2 vsh = __float2half2_rn(vs);
        uint2 t;
        t.x = (unsigned)i;
        t.y = *reinterpret_cast<const unsigned*>(&vsh);
        s_pre[warp][lane] = t;
    }
    __syncwarp();

    // This lane's chunk base; in-loop address = lane_base + i*32 (uint2 units).
    const uint2* __restrict__ lane_base = g_comb + lane;

    __half2 acc0 = __float2half2_rn(0.f);
    __half2 acc1 = __float2half2_rn(0.f);
    __half2 acc2 = __float2half2_rn(0.f);
    __half2 acc3 = __float2half2_rn(0.f);

#pragma unroll 16
    for (int f = 0; f < MAXF; ++f) {
        const uint2 t = s_pre[warp][f];                       // LDS.64 broadcast
        const uint2 p = lane_base[(size_t)t.x * 32];          // IMAD.WIDE + LDG.64
        const __half2 vsh = *reinterpret_cast<const __half2*>(&t.y);

        const __half2 q0 = dec_e4m3x2(p.x);         // dims 0,1
        const __half2 q1 = dec_e4m3x2(p.x >> 16);   // dims 2,3
        const __half2 q2 = dec_e4m3x2(p.y);         // dims 4,5
        const __half2 q3 = dec_e4m3x2(p.y >> 16);   // dims 6,7

        acc0 = __hfma2(q0, vsh, acc0);
        acc1 = __hfma2(q1, vsh, acc1);
        acc2 = __hfma2(q2, vsh, acc2);
        acc3 = __hfma2(q3, vsh, acc3);
    }

    const int col = lane * 8;

    const float2 f0 = __half22float2(acc0);
    const float2 f1 = __half22float2(acc1);
    const float2 f2 = __half22float2(acc2);
    const float2 f3 = __half22float2(acc3);
    const float av[8] = { f0.x, f0.y, f1.x, f1.y, f2.x, f2.y, f3.x, f3.y };

    // Epilogue: exact fp32 biases, clip [0,1], dot with this side's out_w.
    const float4 fb0  = *reinterpret_cast<const float4*>(ft_b  + col);
    const float4 fb1  = *reinterpret_cast<const float4*>(ft_b  + col + 4);
    const float4 ffb0 = *reinterpret_cast<const float4*>(fft_b + col);
    const float4 ffb1 = *reinterpret_cast<const float4*>(fft_b + col + 4);
    const float* w    = out_w + side * FT_OUT;
    const float4 w0   = *reinterpret_cast<const float4*>(w + col);
    const float4 w1   = *reinterpret_cast<const float4*>(w + col + 4);

    const float bias[8] = { fb0.x + ffb0.x, fb0.y + ffb0.y, fb0.z + ffb0.z, fb0.w + ffb0.w,
                            fb1.x + ffb1.x, fb1.y + ffb1.y, fb1.z + ffb1.z, fb1.w + ffb1.w };
    const float wd[8]   = { w0.x, w0.y, w0.z, w0.w, w1.x, w1.y, w1.z, w1.w };

    float dot = 0.f;
#pragma unroll
    for (int j = 0; j < 8; ++j) {
        const float h = fminf(fmaxf(av[j] + bias[j], 0.f), 1.f);
        dot += h * wd[j];
    }

#pragma unroll
    for (int off = 16; off > 0; off >>= 1)
        dot += __shfl_xor_sync(0xffffffffu, dot, off);

    if (lane == 0) s_dot[warp] = dot;
    __syncthreads();

    if (threadIdx.x < 4) {
        const int eo = blockIdx.x * 4 + threadIdx.x;
        if (eo < batch) {
            const float x = s_dot[2 * threadIdx.x] + s_dot[2 * threadIdx.x + 1] + out_b[0];
            out[eo] = 1.0f / (1.0f + expf(-x));
        }
    }
}

extern "C" void kernel_launch(void* const* d_in, const int* in_sizes, int n_in,
                              void* d_out, int out_size)
{
    const float* values = (const float*)d_in[0];
    const int*   stm    = (const int*)  d_in[1];
    const int*   nstm   = (const int*)  d_in[2];
    const float* ft_w   = (const float*)d_in[3];
    const float* ft_b   = (const float*)d_in[4];
    const float* fft_w  = (const float*)d_in[5];
    const float* fft_b  = (const float*)d_in[6];
    const float* out_w  = (const float*)d_in[7];
    const float* out_b  = (const float*)d_in[8];
    float* out = (float*)d_out;

    // Stage 1: combined e4m3 table (one warp per row, 8 rows per block).
    build_table_kernel<<<NUM_FT / 8, 256>>>(ft_w, fft_w);

    // Stage 2: gather + MLP.
    const int batch  = in_sizes[0] / MAXF;   // 8192
    const int blocks = (batch + 3) / 4;
    nnue_halfkp_kernel<<<blocks, 256>>>(values, stm, nstm, ft_b,
                                        fft_b, out_w, out_b, out, batch);
}